// round 2
// baseline (speedup 1.0000x reference)
#include <cuda_runtime.h>

// Fused: QKV proj -> 4-head attention (S=32, D=32) -> out proj -> residual -> LayerNorm
// E=128, S=32, H=4, D=32. BB=2 batches per CTA => 64x128 row tile.
// fp32 everywhere; GEMMs use packed fma.rn.f32x2 (SIMD over K pairs).

#define TE 128
#define TS 32
#define TH 4
#define TD 32
#define BB 2
#define RR 64          // BB*TS rows per CTA
#define NT 256
#define KF 32          // float4 slots per 128-float row

typedef unsigned long long u64;

// smem floats: x(64*128) + q + k + v + w(128*128) = 4*8192 + 16384 = 49152 floats
#define SMEM_BYTES (49152 * 4)

__device__ __forceinline__ void fma2(u64 &acc, u64 a, u64 b) {
    asm("fma.rn.f32x2 %0, %1, %2, %0;" : "+l"(acc) : "l"(a), "l"(b));
}
__device__ __forceinline__ float2 asf2(u64 v) {
    float2 r;
    asm("mov.b64 {%0, %1}, %2;" : "=f"(r.x), "=f"(r.y) : "l"(v));
    return r;
}
__device__ __forceinline__ float wredsum(float v) {
#pragma unroll
    for (int o = 16; o; o >>= 1) v += __shfl_xor_sync(0xffffffffu, v, o);
    return v;
}
__device__ __forceinline__ float wredmax(float v) {
#pragma unroll
    for (int o = 16; o; o >>= 1) v = fmaxf(v, __shfl_xor_sync(0xffffffffu, v, o));
    return v;
}

// Load W [128x128] row-major into smem, XOR-swizzled at float4 granularity:
// slot for column-float4 c of row f is (c ^ (f>>2)). Coalesced global reads,
// conflict-free STS.128 (per-warp: one f, c = lane -> permutation).
__device__ __forceinline__ void load_weight(float4* ws4, const float* __restrict__ W, int tid) {
    const float4* gw = (const float4*)W;
#pragma unroll
    for (int p = 0; p < 16; ++p) {
        int e = p * NT + tid;          // 0..4095
        int f = e >> 5;
        int c = e & 31;
        ws4[f * KF + (c ^ (f >> 2))] = gw[e];
    }
}

// C[64][128] = src @ W^T  (both operands K-major in smem, swizzled).
// Thread (warp w, lane tx): rows r0=w*8 .. r0+7, cols f = tx*4 .. tx*4+3.
// Accumulate in f32x2 pairs over K (even/odd k lanes), reduce at the end.
__device__ __forceinline__ void gemm_acc(const float4* __restrict__ src4,
                                         const float4* __restrict__ ws4,
                                         int r0, int tx, float out[8][4]) {
    u64 acc[8][4];
#pragma unroll
    for (int i = 0; i < 8; ++i)
#pragma unroll
        for (int j = 0; j < 4; ++j) acc[i][j] = 0ull;

#pragma unroll 4
    for (int k4 = 0; k4 < 32; ++k4) {
        ulonglong2 a[8];
#pragma unroll
        for (int i = 0; i < 8; ++i) {
            int r = r0 + i;
            a[i] = *reinterpret_cast<const ulonglong2*>(&src4[r * KF + (k4 ^ (r & 31))]);
        }
        ulonglong2 b[4];
#pragma unroll
        for (int j = 0; j < 4; ++j) {
            int f = tx * 4 + j;
            b[j] = *reinterpret_cast<const ulonglong2*>(&ws4[f * KF + (k4 ^ tx)]);
        }
#pragma unroll
        for (int i = 0; i < 8; ++i)
#pragma unroll
            for (int j = 0; j < 4; ++j) {
                fma2(acc[i][j], a[i].x, b[j].x);
                fma2(acc[i][j], a[i].y, b[j].y);
            }
    }
#pragma unroll
    for (int i = 0; i < 8; ++i)
#pragma unroll
        for (int j = 0; j < 4; ++j) {
            float2 t = asf2(acc[i][j]);
            out[i][j] = t.x + t.y;
        }
}

__global__ void __launch_bounds__(NT, 1)
fused_attn_kernel(const float* __restrict__ inputs,
                  const float* __restrict__ Wq, const float* __restrict__ bq,
                  const float* __restrict__ Wk, const float* __restrict__ bk,
                  const float* __restrict__ Wv, const float* __restrict__ bv,
                  const float* __restrict__ Wo, const float* __restrict__ bo,
                  const float* __restrict__ gamma, const float* __restrict__ beta,
                  float* __restrict__ out)
{
    extern __shared__ float smem[];
    float4* xs4 = (float4*)smem;
    float4* qs4 = xs4 + RR * KF;
    float4* ks4 = qs4 + RR * KF;
    float4* vs4 = ks4 + RR * KF;
    float4* ws4 = vs4 + RR * KF;

    const int tid  = threadIdx.x;
    const int lane = tid & 31;
    const int warp = tid >> 5;
    const int r0   = warp * 8;
    const int tx   = lane;

    // ---- load x tile (swizzled) ----
    const float4* gx = (const float4*)inputs + (size_t)blockIdx.x * (RR * KF);
#pragma unroll
    for (int p = 0; p < (RR * KF) / NT; ++p) {   // 8 passes
        int e = p * NT + tid;
        int r = e >> 5;
        int c = e & 31;
        xs4[r * KF + (c ^ (r & 31))] = gx[e];
    }
    load_weight(ws4, Wq, tid);
    __syncthreads();

    float res[8][4];
    const float qscale = 0.17677669529663687f;   // 1/sqrt(32)

    // ---- Q = (x @ Wq^T + bq) * qscale ----
    gemm_acc(xs4, ws4, r0, tx, res);
    {
        float4 b4 = ((const float4*)bq)[tx];
#pragma unroll
        for (int i = 0; i < 8; ++i) {
            int r = r0 + i;
            float4 o;
            o.x = (res[i][0] + b4.x) * qscale;
            o.y = (res[i][1] + b4.y) * qscale;
            o.z = (res[i][2] + b4.z) * qscale;
            o.w = (res[i][3] + b4.w) * qscale;
            qs4[r * KF + (tx ^ (r & 31))] = o;
        }
    }
    __syncthreads();
    load_weight(ws4, Wk, tid);
    __syncthreads();

    // ---- K ----
    gemm_acc(xs4, ws4, r0, tx, res);
    {
        float4 b4 = ((const float4*)bk)[tx];
#pragma unroll
        for (int i = 0; i < 8; ++i) {
            int r = r0 + i;
            float4 o;
            o.x = res[i][0] + b4.x;
            o.y = res[i][1] + b4.y;
            o.z = res[i][2] + b4.z;
            o.w = res[i][3] + b4.w;
            ks4[r * KF + (tx ^ (r & 31))] = o;
        }
    }
    __syncthreads();
    load_weight(ws4, Wv, tid);
    __syncthreads();

    // ---- V ----
    gemm_acc(xs4, ws4, r0, tx, res);
    {
        float4 b4 = ((const float4*)bv)[tx];
#pragma unroll
        for (int i = 0; i < 8; ++i) {
            int r = r0 + i;
            float4 o;
            o.x = res[i][0] + b4.x;
            o.y = res[i][1] + b4.y;
            o.z = res[i][2] + b4.z;
            o.w = res[i][3] + b4.w;
            vs4[r * KF + (tx ^ (r & 31))] = o;
        }
    }
    __syncthreads();

    // ws free now; preload Wo while attention runs (attention never touches ws)
    load_weight(ws4, Wo, tid);

    // ---- attention: warp = (batch bb, head h); ctx overwrites q in-place ----
    {
        const int bb    = warp >> 2;       // 0..1
        const int h     = warp & 3;        // 0..3
        const int rbase = bb * 32;
        const int c4b   = h * 8;           // float4 col base of this head

        float kreg[32], vreg[32];
        // K row t = lane, all 32 d values
        {
            int rk = rbase + lane;
#pragma unroll
            for (int c = 0; c < 8; ++c) {
                float4 kv = ks4[rk * KF + ((c4b + c) ^ (rk & 31))];
                kreg[c * 4 + 0] = kv.x; kreg[c * 4 + 1] = kv.y;
                kreg[c * 4 + 2] = kv.z; kreg[c * 4 + 3] = kv.w;
            }
        }
        // V column d = lane, all 32 t values (scalar gathers, conflict-free by swizzle)
        {
            const float* vsf = (const float*)vs4;
            int cslot = c4b + (lane >> 2);
            int sub = lane & 3;
#pragma unroll
            for (int t = 0; t < 32; ++t) {
                int r = rbase + t;
                vreg[t] = vsf[r * TE + ((cslot ^ (r & 31)) << 2) + sub];
            }
        }

        float* qsf = (float*)qs4;
        const int cslot = c4b + (lane >> 2);
        const int sub = lane & 3;
#pragma unroll 1
        for (int s = 0; s < 32; ++s) {
            int rq = rbase + s;
            // score(s, t=lane) = q[s,:] . k[t,:]
            float sc = 0.f;
#pragma unroll
            for (int c = 0; c < 8; ++c) {
                float4 qv = qs4[rq * KF + ((c4b + c) ^ (rq & 31))];  // broadcast
                sc = fmaf(qv.x, kreg[c * 4 + 0],
                     fmaf(qv.y, kreg[c * 4 + 1],
                     fmaf(qv.z, kreg[c * 4 + 2],
                     fmaf(qv.w, kreg[c * 4 + 3], sc))));
            }
            float m = wredmax(sc);
            float p = __expf(sc - m);
            float psum = wredsum(p);
            p = p / psum;
            // ctx[s, d=lane] = sum_t p_t * v[t, d]
            float ctx = 0.f;
#pragma unroll
            for (int t = 0; t < 32; ++t)
                ctx = fmaf(__shfl_sync(0xffffffffu, p, t), vreg[t], ctx);
            // overwrite q row s (done being read) with ctx
            qsf[rq * TE + ((cslot ^ (rq & 31)) << 2) + sub] = ctx;
        }
    }
    __syncthreads();

    // ---- out = ctx @ Wo^T + bo + x, then LayerNorm ----
    gemm_acc(qs4, ws4, r0, tx, res);
    {
        float4 b4  = ((const float4*)bo)[tx];
        float4 g4  = ((const float4*)gamma)[tx];
        float4 be4 = ((const float4*)beta)[tx];
        float4* gout = (float4*)out + (size_t)blockIdx.x * (RR * KF);
#pragma unroll
        for (int i = 0; i < 8; ++i) {
            int r = r0 + i;
            float4 xr = xs4[r * KF + (tx ^ (r & 31))];
            float ox = res[i][0] + b4.x + xr.x;
            float oy = res[i][1] + b4.y + xr.y;
            float oz = res[i][2] + b4.z + xr.z;
            float ow = res[i][3] + b4.w + xr.w;
            float mu = wredsum(ox + oy + oz + ow) * (1.f / 128.f);
            float dx = ox - mu, dy = oy - mu, dz = oz - mu, dw = ow - mu;
            float var = wredsum(dx * dx + dy * dy + dz * dz + dw * dw) * (1.f / 128.f);
            float rstd = rsqrtf(var + 1e-5f);
            float4 w;
            w.x = dx * rstd * g4.x + be4.x;
            w.y = dy * rstd * g4.y + be4.y;
            w.z = dz * rstd * g4.z + be4.z;
            w.w = dw * rstd * g4.w + be4.w;
            gout[r * KF + tx] = w;
        }
    }
}

extern "C" void kernel_launch(void* const* d_in, const int* in_sizes, int n_in,
                              void* d_out, int out_size) {
    const float* inputs = (const float*)d_in[0];
    const float* Wq = (const float*)d_in[1];
    const float* bq = (const float*)d_in[2];
    const float* Wk = (const float*)d_in[3];
    const float* bk = (const float*)d_in[4];
    const float* Wv = (const float*)d_in[5];
    const float* bv = (const float*)d_in[6];
    const float* Wo = (const float*)d_in[7];
    const float* bo = (const float*)d_in[8];
    const float* gamma = (const float*)d_in[9];
    const float* beta  = (const float*)d_in[10];
    float* outp = (float*)d_out;

    int B = in_sizes[0] / 4096;           // 16384
    int grid = B / BB;                    // 8192

    cudaFuncSetAttribute(fused_attn_kernel,
                         cudaFuncAttributeMaxDynamicSharedMemorySize, SMEM_BYTES);
    fused_attn_kernel<<<grid, NT, SMEM_BYTES>>>(inputs, Wq, bq, Wk, bk, Wv, bv,
                                                Wo, bo, gamma, beta, outp);
}

// round 3
// speedup vs baseline: 1.0007x; 1.0007x over previous
#include <cuda_runtime.h>

// Fused: QKV proj -> 4-head attention (S=32, D=32) -> out proj -> residual -> LayerNorm
// E=128, S=32, H=4, D=32. BB=2 batches per CTA => 64x128 row tile.
// fp32 everywhere; GEMMs use packed fma.rn.f32x2 (SIMD over K pairs).

#define TE 128
#define TS 32
#define TH 4
#define TD 32
#define BB 2
#define RR 64          // BB*TS rows per CTA
#define NT 256
#define KF 32          // float4 slots per 128-float row

typedef unsigned long long u64;

// smem floats: x(64*128) + q + k + v + w(128*128) = 4*8192 + 16384 = 49152 floats
#define SMEM_BYTES (49152 * 4)

__device__ __forceinline__ void fma2(u64 &acc, u64 a, u64 b) {
    asm("fma.rn.f32x2 %0, %1, %2, %0;" : "+l"(acc) : "l"(a), "l"(b));
}
__device__ __forceinline__ float2 asf2(u64 v) {
    float2 r;
    asm("mov.b64 {%0, %1}, %2;" : "=f"(r.x), "=f"(r.y) : "l"(v));
    return r;
}
__device__ __forceinline__ float wredsum(float v) {
#pragma unroll
    for (int o = 16; o; o >>= 1) v += __shfl_xor_sync(0xffffffffu, v, o);
    return v;
}
__device__ __forceinline__ float wredmax(float v) {
#pragma unroll
    for (int o = 16; o; o >>= 1) v = fmaxf(v, __shfl_xor_sync(0xffffffffu, v, o));
    return v;
}

// Load W [128x128] row-major into smem, XOR-swizzled at float4 granularity:
// slot for column-float4 c of row f is (c ^ (f>>2)). Coalesced global reads,
// conflict-free STS.128 (per-warp: one f, c = lane -> permutation).
__device__ __forceinline__ void load_weight(float4* ws4, const float* __restrict__ W, int tid) {
    const float4* gw = (const float4*)W;
#pragma unroll
    for (int p = 0; p < 16; ++p) {
        int e = p * NT + tid;          // 0..4095
        int f = e >> 5;
        int c = e & 31;
        ws4[f * KF + (c ^ (f >> 2))] = gw[e];
    }
}

// C[64][128] = src @ W^T  (both operands K-major in smem, swizzled).
// Thread (warp w, lane tx): rows r0=w*8 .. r0+7, cols f = tx*4 .. tx*4+3.
// Accumulate in f32x2 pairs over K (even/odd k lanes), reduce at the end.
__device__ __forceinline__ void gemm_acc(const float4* __restrict__ src4,
                                         const float4* __restrict__ ws4,
                                         int r0, int tx, float out[8][4]) {
    u64 acc[8][4];
#pragma unroll
    for (int i = 0; i < 8; ++i)
#pragma unroll
        for (int j = 0; j < 4; ++j) acc[i][j] = 0ull;

#pragma unroll 4
    for (int k4 = 0; k4 < 32; ++k4) {
        ulonglong2 a[8];
#pragma unroll
        for (int i = 0; i < 8; ++i) {
            int r = r0 + i;
            a[i] = *reinterpret_cast<const ulonglong2*>(&src4[r * KF + (k4 ^ (r & 31))]);
        }
        ulonglong2 b[4];
#pragma unroll
        for (int j = 0; j < 4; ++j) {
            int f = tx * 4 + j;
            b[j] = *reinterpret_cast<const ulonglong2*>(&ws4[f * KF + (k4 ^ tx)]);
        }
#pragma unroll
        for (int i = 0; i < 8; ++i)
#pragma unroll
            for (int j = 0; j < 4; ++j) {
                fma2(acc[i][j], a[i].x, b[j].x);
                fma2(acc[i][j], a[i].y, b[j].y);
            }
    }
#pragma unroll
    for (int i = 0; i < 8; ++i)
#pragma unroll
        for (int j = 0; j < 4; ++j) {
            float2 t = asf2(acc[i][j]);
            out[i][j] = t.x + t.y;
        }
}

__global__ void __launch_bounds__(NT, 1)
fused_attn_kernel(const float* __restrict__ inputs,
                  const float* __restrict__ Wq, const float* __restrict__ bq,
                  const float* __restrict__ Wk, const float* __restrict__ bk,
                  const float* __restrict__ Wv, const float* __restrict__ bv,
                  const float* __restrict__ Wo, const float* __restrict__ bo,
                  const float* __restrict__ gamma, const float* __restrict__ beta,
                  float* __restrict__ out)
{
    extern __shared__ float smem[];
    float4* xs4 = (float4*)smem;
    float4* qs4 = xs4 + RR * KF;
    float4* ks4 = qs4 + RR * KF;
    float4* vs4 = ks4 + RR * KF;
    float4* ws4 = vs4 + RR * KF;

    const int tid  = threadIdx.x;
    const int lane = tid & 31;
    const int warp = tid >> 5;
    const int r0   = warp * 8;
    const int tx   = lane;

    // ---- load x tile (swizzled) ----
    const float4* gx = (const float4*)inputs + (size_t)blockIdx.x * (RR * KF);
#pragma unroll
    for (int p = 0; p < (RR * KF) / NT; ++p) {   // 8 passes
        int e = p * NT + tid;
        int r = e >> 5;
        int c = e & 31;
        xs4[r * KF + (c ^ (r & 31))] = gx[e];
    }
    load_weight(ws4, Wq, tid);
    __syncthreads();

    float res[8][4];
    const float qscale = 0.17677669529663687f;   // 1/sqrt(32)

    // ---- Q = (x @ Wq^T + bq) * qscale ----
    gemm_acc(xs4, ws4, r0, tx, res);
    {
        float4 b4 = ((const float4*)bq)[tx];
#pragma unroll
        for (int i = 0; i < 8; ++i) {
            int r = r0 + i;
            float4 o;
            o.x = (res[i][0] + b4.x) * qscale;
            o.y = (res[i][1] + b4.y) * qscale;
            o.z = (res[i][2] + b4.z) * qscale;
            o.w = (res[i][3] + b4.w) * qscale;
            qs4[r * KF + (tx ^ (r & 31))] = o;
        }
    }
    __syncthreads();
    load_weight(ws4, Wk, tid);
    __syncthreads();

    // ---- K ----
    gemm_acc(xs4, ws4, r0, tx, res);
    {
        float4 b4 = ((const float4*)bk)[tx];
#pragma unroll
        for (int i = 0; i < 8; ++i) {
            int r = r0 + i;
            float4 o;
            o.x = res[i][0] + b4.x;
            o.y = res[i][1] + b4.y;
            o.z = res[i][2] + b4.z;
            o.w = res[i][3] + b4.w;
            ks4[r * KF + (tx ^ (r & 31))] = o;
        }
    }
    __syncthreads();
    load_weight(ws4, Wv, tid);
    __syncthreads();

    // ---- V ----
    gemm_acc(xs4, ws4, r0, tx, res);
    {
        float4 b4 = ((const float4*)bv)[tx];
#pragma unroll
        for (int i = 0; i < 8; ++i) {
            int r = r0 + i;
            float4 o;
            o.x = res[i][0] + b4.x;
            o.y = res[i][1] + b4.y;
            o.z = res[i][2] + b4.z;
            o.w = res[i][3] + b4.w;
            vs4[r * KF + (tx ^ (r & 31))] = o;
        }
    }
    __syncthreads();

    // ws free now; preload Wo while attention runs (attention never touches ws)
    load_weight(ws4, Wo, tid);

    // ---- attention: warp = (batch bb, head h); ctx overwrites q in-place ----
    {
        const int bb    = warp >> 2;       // 0..1
        const int h     = warp & 3;        // 0..3
        const int rbase = bb * 32;
        const int c4b   = h * 8;           // float4 col base of this head

        float kreg[32], vreg[32];
        // K row t = lane, all 32 d values
        {
            int rk = rbase + lane;
#pragma unroll
            for (int c = 0; c < 8; ++c) {
                float4 kv = ks4[rk * KF + ((c4b + c) ^ (rk & 31))];
                kreg[c * 4 + 0] = kv.x; kreg[c * 4 + 1] = kv.y;
                kreg[c * 4 + 2] = kv.z; kreg[c * 4 + 3] = kv.w;
            }
        }
        // V column d = lane, all 32 t values (scalar gathers, conflict-free by swizzle)
        {
            const float* vsf = (const float*)vs4;
            int cslot = c4b + (lane >> 2);
            int sub = lane & 3;
#pragma unroll
            for (int t = 0; t < 32; ++t) {
                int r = rbase + t;
                vreg[t] = vsf[r * TE + ((cslot ^ (r & 31)) << 2) + sub];
            }
        }

        float* qsf = (float*)qs4;
        const int cslot = c4b + (lane >> 2);
        const int sub = lane & 3;
#pragma unroll 1
        for (int s = 0; s < 32; ++s) {
            int rq = rbase + s;
            // score(s, t=lane) = q[s,:] . k[t,:]
            float sc = 0.f;
#pragma unroll
            for (int c = 0; c < 8; ++c) {
                float4 qv = qs4[rq * KF + ((c4b + c) ^ (rq & 31))];  // broadcast
                sc = fmaf(qv.x, kreg[c * 4 + 0],
                     fmaf(qv.y, kreg[c * 4 + 1],
                     fmaf(qv.z, kreg[c * 4 + 2],
                     fmaf(qv.w, kreg[c * 4 + 3], sc))));
            }
            float m = wredmax(sc);
            float p = __expf(sc - m);
            float psum = wredsum(p);
            p = p / psum;
            // ctx[s, d=lane] = sum_t p_t * v[t, d]
            float ctx = 0.f;
#pragma unroll
            for (int t = 0; t < 32; ++t)
                ctx = fmaf(__shfl_sync(0xffffffffu, p, t), vreg[t], ctx);
            // overwrite q row s (done being read) with ctx
            qsf[rq * TE + ((cslot ^ (rq & 31)) << 2) + sub] = ctx;
        }
    }
    __syncthreads();

    // ---- out = ctx @ Wo^T + bo + x, then LayerNorm ----
    gemm_acc(qs4, ws4, r0, tx, res);
    {
        float4 b4  = ((const float4*)bo)[tx];
        float4 g4  = ((const float4*)gamma)[tx];
        float4 be4 = ((const float4*)beta)[tx];
        float4* gout = (float4*)out + (size_t)blockIdx.x * (RR * KF);
#pragma unroll
        for (int i = 0; i < 8; ++i) {
            int r = r0 + i;
            float4 xr = xs4[r * KF + (tx ^ (r & 31))];
            float ox = res[i][0] + b4.x + xr.x;
            float oy = res[i][1] + b4.y + xr.y;
            float oz = res[i][2] + b4.z + xr.z;
            float ow = res[i][3] + b4.w + xr.w;
            float mu = wredsum(ox + oy + oz + ow) * (1.f / 128.f);
            float dx = ox - mu, dy = oy - mu, dz = oz - mu, dw = ow - mu;
            float var = wredsum(dx * dx + dy * dy + dz * dz + dw * dw) * (1.f / 128.f);
            float rstd = rsqrtf(var + 1e-5f);
            float4 w;
            w.x = dx * rstd * g4.x + be4.x;
            w.y = dy * rstd * g4.y + be4.y;
            w.z = dz * rstd * g4.z + be4.z;
            w.w = dw * rstd * g4.w + be4.w;
            gout[r * KF + tx] = w;
        }
    }
}

extern "C" void kernel_launch(void* const* d_in, const int* in_sizes, int n_in,
                              void* d_out, int out_size) {
    const float* inputs = (const float*)d_in[0];
    const float* Wq = (const float*)d_in[1];
    const float* bq = (const float*)d_in[2];
    const float* Wk = (const float*)d_in[3];
    const float* bk = (const float*)d_in[4];
    const float* Wv = (const float*)d_in[5];
    const float* bv = (const float*)d_in[6];
    const float* Wo = (const float*)d_in[7];
    const float* bo = (const float*)d_in[8];
    const float* gamma = (const float*)d_in[9];
    const float* beta  = (const float*)d_in[10];
    float* outp = (float*)d_out;

    int B = in_sizes[0] / 4096;           // 16384
    int grid = B / BB;                    // 8192

    cudaFuncSetAttribute(fused_attn_kernel,
                         cudaFuncAttributeMaxDynamicSharedMemorySize, SMEM_BYTES);
    fused_attn_kernel<<<grid, NT, SMEM_BYTES>>>(inputs, Wq, bq, Wk, bk, Wv, bv,
                                                Wo, bo, gamma, beta, outp);
}